// round 4
// baseline (speedup 1.0000x reference)
#include <cuda_runtime.h>
#include <math.h>
#include <stdint.h>

#define T 4096
#define D 1024
#define H 16
#define DH 64
#define L 32

#define VSTR 72   // V smem row stride in words: 72 % 32 == 8 -> conflict-free scalar reads

// Scratch (allocation-free rule: __device__ globals)
__device__ float g_Qh[H * T * DH];
__device__ float g_Kh[H * T * DH];
__device__ float g_Vh[H * T * DH];
__device__ float g_Vals[T * D];

__device__ __forceinline__ uint32_t f2tf(float f) {
    uint32_t r;
    asm("cvt.rna.tf32.f32 %0, %1;" : "=r"(r) : "f"(f));
    return r;
}

__device__ __forceinline__ void mma_tf32(float c[4], uint32_t a0, uint32_t a1,
                                         uint32_t a2, uint32_t a3,
                                         uint32_t b0, uint32_t b1) {
    asm volatile(
        "mma.sync.aligned.m16n8k8.row.col.f32.tf32.tf32.f32 "
        "{%0,%1,%2,%3}, {%4,%5,%6,%7}, {%8,%9}, {%0,%1,%2,%3};\n"
        : "+f"(c[0]), "+f"(c[1]), "+f"(c[2]), "+f"(c[3])
        : "r"(a0), "r"(a1), "r"(a2), "r"(a3), "r"(b0), "r"(b1));
}

__device__ __forceinline__ void ldsm4(uint32_t& d0, uint32_t& d1, uint32_t& d2,
                                      uint32_t& d3, uint32_t saddr) {
    asm volatile(
        "ldmatrix.sync.aligned.m8n8.x4.shared.b16 {%0,%1,%2,%3}, [%4];"
        : "=r"(d0), "=r"(d1), "=r"(d2), "=r"(d3)
        : "r"(saddr));
}

__device__ __forceinline__ void cp16(uint32_t dst, const void* src) {
    asm volatile("cp.async.cg.shared.global [%0], [%1], 16;\n"
                 :: "r"(dst), "l"(src));
}

// ---------------------------------------------------------------------------
// Projection GEMM on tensor cores (tf32) with ldmatrix fragment loads.
// out = X[M,K] @ W[N,K]^T.  M=4096, N=1024, K=1024.
// Block tile 128x64, BK=32. 256 threads = 8 warps (4 M x 2 N), warp tile 32x32.
// mode 0: plain row-major out [T,1024].
// mode 1: RoPE epilogue + head-major out [H][T][DH] (BN==DH so bx == head).
// ---------------------------------------------------------------------------
__global__ __launch_bounds__(256) void proj_kernel(
    const float* __restrict__ X, const float* __restrict__ W,
    const float* __restrict__ freqs, float* __restrict__ out, int mode)
{
    __shared__ uint32_t As[128 * 32];
    __shared__ uint32_t Bs[64 * 32];

    const int tid = threadIdx.x;
    const int lane = tid & 31;
    const int w = tid >> 5;
    const int gid = lane >> 2;   // 0..7
    const int tig = lane & 3;    // 0..3
    const int wm = w >> 1;       // 0..3
    const int wn = w & 1;        // 0..1
    const int bx = blockIdx.x, by = blockIdx.y;

    const int lsub = lane >> 3;
    const int lr = lane & 7;
    const int khA = lsub >> 1;
    const int khB = lsub & 1;

    const uint32_t as_s = (uint32_t)__cvta_generic_to_shared(As);
    const uint32_t bs_s = (uint32_t)__cvta_generic_to_shared(Bs);

    uint32_t aA[2];
#pragma unroll
    for (int mt = 0; mt < 2; mt++) {
        int rowA = wm * 32 + mt * 16 + lr + ((lsub & 1) << 3);
        aA[mt] = as_s + rowA * 128;
    }
    uint32_t bB[2];
#pragma unroll
    for (int np = 0; np < 2; np++) {
        int n = wn * 32 + np * 16 + lr + ((lsub >> 1) << 3);
        bB[np] = bs_s + n * 128;
    }

    float acc[2][4][4];
#pragma unroll
    for (int mt = 0; mt < 2; mt++)
#pragma unroll
        for (int nt = 0; nt < 4; nt++)
#pragma unroll
            for (int r = 0; r < 4; r++) acc[mt][nt][r] = 0.f;

    int am[4], akg[4], bm[2], bkg[2];
#pragma unroll
    for (int i = 0; i < 4; i++) {
        int f = tid + i * 256;
        am[i] = f >> 3;
        akg[i] = f & 7;
    }
#pragma unroll
    for (int i = 0; i < 2; i++) {
        int f = tid + i * 256;
        bm[i] = f >> 3;
        bkg[i] = f & 7;
    }

    float4 ra[4], rb[2];
#pragma unroll
    for (int i = 0; i < 4; i++)
        ra[i] = *(const float4*)(X + (size_t)(by * 128 + am[i]) * D + akg[i] * 4);
#pragma unroll
    for (int i = 0; i < 2; i++)
        rb[i] = *(const float4*)(W + (size_t)(bx * 64 + bm[i]) * D + bkg[i] * 4);

    for (int kk = 0; kk < 32; kk++) {
        __syncthreads();
#pragma unroll
        for (int i = 0; i < 4; i++) {
            uint4 u = make_uint4(f2tf(ra[i].x), f2tf(ra[i].y), f2tf(ra[i].z), f2tf(ra[i].w));
            *(uint4*)&As[am[i] * 32 + ((akg[i] ^ (am[i] & 7)) << 2)] = u;
        }
#pragma unroll
        for (int i = 0; i < 2; i++) {
            uint4 u = make_uint4(f2tf(rb[i].x), f2tf(rb[i].y), f2tf(rb[i].z), f2tf(rb[i].w));
            *(uint4*)&Bs[bm[i] * 32 + ((bkg[i] ^ (bm[i] & 7)) << 2)] = u;
        }
        __syncthreads();

        if (kk < 31) {
            int k0 = (kk + 1) * 32;
#pragma unroll
            for (int i = 0; i < 4; i++)
                ra[i] = *(const float4*)(X + (size_t)(by * 128 + am[i]) * D + k0 + akg[i] * 4);
#pragma unroll
            for (int i = 0; i < 2; i++)
                rb[i] = *(const float4*)(W + (size_t)(bx * 64 + bm[i]) * D + k0 + bkg[i] * 4);
        }

#pragma unroll
        for (int ks = 0; ks < 4; ks++) {
            uint32_t a[2][4];
#pragma unroll
            for (int mt = 0; mt < 2; mt++)
                ldsm4(a[mt][0], a[mt][1], a[mt][2], a[mt][3],
                      aA[mt] + (((2 * ks + khA) ^ lr) << 4));
#pragma unroll
            for (int np = 0; np < 2; np++) {
                uint32_t b00, b01, b10, b11;
                ldsm4(b00, b01, b10, b11, bB[np] + (((2 * ks + khB) ^ lr) << 4));
#pragma unroll
                for (int mt = 0; mt < 2; mt++) {
                    mma_tf32(acc[mt][2 * np], a[mt][0], a[mt][1], a[mt][2], a[mt][3], b00, b01);
                    mma_tf32(acc[mt][2 * np + 1], a[mt][0], a[mt][1], a[mt][2], a[mt][3], b10, b11);
                }
            }
        }
    }

    if (mode == 0) {
#pragma unroll
        for (int mt = 0; mt < 2; mt++) {
#pragma unroll
            for (int rh = 0; rh < 2; rh++) {
                int t = by * 128 + wm * 32 + mt * 16 + gid + rh * 8;
#pragma unroll
                for (int nt = 0; nt < 4; nt++) {
                    int col = bx * 64 + wn * 32 + nt * 8 + tig * 2;
                    float2 v = make_float2(acc[mt][nt][rh * 2], acc[mt][nt][rh * 2 + 1]);
                    *(float2*)(out + (size_t)t * D + col) = v;
                }
            }
        }
    } else {
        const int h = bx;
        if (wn == 0) {
#pragma unroll
            for (int mt = 0; mt < 2; mt++) {
#pragma unroll
                for (int rh = 0; rh < 2; rh++) {
                    int t = by * 128 + wm * 32 + mt * 16 + gid + rh * 8;
#pragma unroll
                    for (int nt = 0; nt < 4; nt++) {
                        int l = nt * 8 + tig * 2;
                        float2 f2 = *(const float2*)(freqs + (size_t)t * L + l);
                        float x0 = acc[mt][nt][rh * 2];
                        float x1 = acc[mt][nt][rh * 2 + 1];
                        float p0 = acc[mt][nt ^ 2][rh * 2];
                        float p1 = acc[mt][nt ^ 2][rh * 2 + 1];
                        float r0 = (nt < 2) ? -p0 : p0;
                        float r1 = (nt < 2) ? -p1 : p1;
                        float2 v;
                        v.x = x0 * __cosf(f2.x) + r0 * __sinf(f2.x);
                        v.y = x1 * __cosf(f2.y) + r1 * __sinf(f2.y);
                        *(float2*)(out + (size_t)h * T * DH + (size_t)t * DH + l) = v;
                    }
                }
            }
        } else {
#pragma unroll
            for (int mt = 0; mt < 2; mt++) {
#pragma unroll
                for (int rh = 0; rh < 2; rh++) {
                    int t = by * 128 + wm * 32 + mt * 16 + gid + rh * 8;
#pragma unroll
                    for (int nt = 0; nt < 4; nt++) {
                        int col = 32 + nt * 8 + tig * 2;
                        float2 v = make_float2(acc[mt][nt][rh * 2], acc[mt][nt][rh * 2 + 1]);
                        *(float2*)(out + (size_t)h * T * DH + (size_t)t * DH + col) = v;
                    }
                }
            }
        }
    }
}

// ---------------------------------------------------------------------------
// Causal flash attention, tf32 tensor cores + ldmatrix + cp.async pipeline.
// Block = (head, 64-query tile), 128 threads = 4 warps, each warp 16 q-rows.
// K/V staged raw fp32 (mma truncates to tf32); Q and P are RNA tf32.
// ---------------------------------------------------------------------------
__global__ __launch_bounds__(128) void attn_kernel(
    const float* __restrict__ Q, const float* __restrict__ Kg,
    const float* __restrict__ Vg, float* __restrict__ vals)
{
    extern __shared__ uint32_t sm[];
    uint32_t* Qs = sm;                      // 4096 w, tf32, xor-swizzled
    uint32_t* Ksb[2] = { sm + 4096, sm + 8192 };     // raw fp32, swizzled for ldsm
    uint32_t* Vsb[2] = { sm + 12288, sm + 12288 + 64 * VSTR };  // raw fp32, stride 72
    uint32_t* Ps = sm + 12288 + 2 * 64 * VSTR;       // 4096 w tf32

    const int tid = threadIdx.x;
    const int lane = tid & 31;
    const int w = tid >> 5;
    const int gid = lane >> 2;
    const int tig = lane & 3;
    const int qb = 63 - blockIdx.x;   // long tiles first
    const int h = blockIdx.y;

    const int lsub = lane >> 3;
    const int lr = lane & 7;
    const int khA = lsub >> 1;
    const int khB = lsub & 1;

    const uint32_t qs_s = (uint32_t)__cvta_generic_to_shared(Qs);
    const uint32_t ps_s = (uint32_t)__cvta_generic_to_shared(Ps);
    const uint32_t ks_s0 = (uint32_t)__cvta_generic_to_shared(Ksb[0]);
    const uint32_t ks_s1 = (uint32_t)__cvta_generic_to_shared(Ksb[1]);
    const uint32_t vs_s0 = (uint32_t)__cvta_generic_to_shared(Vsb[0]);
    const uint32_t vs_s1 = (uint32_t)__cvta_generic_to_shared(Vsb[1]);

    const int rowA = w * 16 + lr + ((lsub & 1) << 3);
    const uint32_t aQ = qs_s + rowA * 256;
    const uint32_t aP = ps_s + rowA * 256;
    const int rowBr = lr + ((lsub >> 1) << 3);

    const float* Qh = Q + (size_t)h * T * DH;
    const float* Kh = Kg + (size_t)h * T * DH;
    const float* Vh = Vg + (size_t)h * T * DH;

    // staging indices (8 x (K16B + V16B) per thread)
    const int sm_m = tid >> 4;        // base row (advance by 8 per i)
    const int sm_kg = tid & 15;

    // prologue: issue cp.async for jb=0
    {
        uint32_t kd = ks_s0, vd = vs_s0;
#pragma unroll
        for (int i = 0; i < 8; i++) {
            int m = sm_m + i * 8;
            cp16(kd + (m * 64 + (((sm_kg) ^ (m & 7)) << 2)) * 4,
                 Kh + (size_t)m * DH + sm_kg * 4);
            cp16(vd + (m * VSTR + sm_kg * 4) * 4,
                 Vh + (size_t)m * DH + sm_kg * 4);
        }
    }
    asm volatile("cp.async.commit_group;\n");

    // Q tile: LDG + RNA tf32 + swizzled STS
#pragma unroll
    for (int i = 0; i < 8; i++) {
        int f = tid + i * 128;
        int m = f >> 4, kg = f & 15;
        float4 v4 = *(const float4*)(Qh + (size_t)(qb * 64 + m) * DH + kg * 4);
        uint4 u = make_uint4(f2tf(v4.x * 0.125f), f2tf(v4.y * 0.125f),
                             f2tf(v4.z * 0.125f), f2tf(v4.w * 0.125f));
        *(uint4*)&Qs[m * 64 + ((kg ^ (m & 7)) << 2)] = u;
    }

    float o[8][4];
#pragma unroll
    for (int nt = 0; nt < 8; nt++)
#pragma unroll
        for (int r = 0; r < 4; r++) o[nt][r] = 0.f;
    float mr[2] = {-1e30f, -1e30f};
    float lr2[2] = {0.f, 0.f};

    const int r0 = w * 16 + gid;

    for (int jb = 0; jb <= qb; jb++) {
        const int cur = jb & 1;
        __syncthreads();   // all warps done with buffer (1-cur) from iter jb-1
        if (jb < qb) {
            uint32_t kd = cur ? ks_s0 : ks_s1;
            uint32_t vd = cur ? vs_s0 : vs_s1;
            const float* Kp = Kh + (size_t)(jb + 1) * 64 * DH;
            const float* Vp = Vh + (size_t)(jb + 1) * 64 * DH;
#pragma unroll
            for (int i = 0; i < 8; i++) {
                int m = sm_m + i * 8;
                cp16(kd + (m * 64 + ((sm_kg ^ (m & 7)) << 2)) * 4,
                     Kp + (size_t)m * DH + sm_kg * 4);
                cp16(vd + (m * VSTR + sm_kg * 4) * 4,
                     Vp + (size_t)m * DH + sm_kg * 4);
            }
            asm volatile("cp.async.commit_group;\n");
            asm volatile("cp.async.wait_group 1;\n");
        } else {
            asm volatile("cp.async.wait_group 0;\n");
        }
        __syncthreads();   // jb's K/V visible to all

        const uint32_t ks_s = cur ? ks_s1 : ks_s0;
        const uint32_t* Vsc = Vsb[cur];

        // S = Q K^T
        float s[8][4];
#pragma unroll
        for (int nt = 0; nt < 8; nt++)
#pragma unroll
            for (int r = 0; r < 4; r++) s[nt][r] = 0.f;

        uint32_t bK[4];
#pragma unroll
        for (int np = 0; np < 4; np++)
            bK[np] = ks_s + (np * 16 + rowBr) * 256;

#pragma unroll
        for (int ks = 0; ks < 8; ks++) {
            uint32_t a0, a1, a2, a3;
            ldsm4(a0, a1, a2, a3, aQ + (((2 * ks + khA) ^ lr) << 4));
#pragma unroll
            for (int np = 0; np < 4; np++) {
                uint32_t b00, b01, b10, b11;
                ldsm4(b00, b01, b10, b11, bK[np] + (((2 * ks + khB) ^ lr) << 4));
                mma_tf32(s[2 * np], a0, a1, a2, a3, b00, b01);
                mma_tf32(s[2 * np + 1], a0, a1, a2, a3, b10, b11);
            }
        }

        if (jb == qb) {
#pragma unroll
            for (int nt = 0; nt < 8; nt++)
#pragma unroll
                for (int r = 0; r < 4; r++) {
                    int col = nt * 8 + tig * 2 + (r & 1);
                    int row = w * 16 + gid + ((r & 2) ? 8 : 0);
                    if (col > row) s[nt][r] = -1e30f;
                }
        }

        // online softmax (two rows per thread)
#pragma unroll
        for (int half = 0; half < 2; half++) {
            float mx = -1e30f;
#pragma unroll
            for (int nt = 0; nt < 8; nt++) {
                mx = fmaxf(mx, s[nt][half * 2]);
                mx = fmaxf(mx, s[nt][half * 2 + 1]);
            }
            mx = fmaxf(mx, __shfl_xor_sync(0xffffffffu, mx, 1));
            mx = fmaxf(mx, __shfl_xor_sync(0xffffffffu, mx, 2));
            float mnew = fmaxf(mr[half], mx);
            float alpha = __expf(mr[half] - mnew);
            mr[half] = mnew;
            float rs = 0.f;
#pragma unroll
            for (int nt = 0; nt < 8; nt++) {
                float p0 = __expf(s[nt][half * 2] - mnew);
                float p1 = __expf(s[nt][half * 2 + 1] - mnew);
                s[nt][half * 2] = p0;
                s[nt][half * 2 + 1] = p1;
                rs += p0 + p1;
            }
            rs += __shfl_xor_sync(0xffffffffu, rs, 1);
            rs += __shfl_xor_sync(0xffffffffu, rs, 2);
            lr2[half] = lr2[half] * alpha + rs;
#pragma unroll
            for (int nt = 0; nt < 8; nt++) {
                o[nt][half * 2] *= alpha;
                o[nt][half * 2 + 1] *= alpha;
            }
        }

        // write P (RNA tf32) to warp-private smem rows
#pragma unroll
        for (int nt = 0; nt < 8; nt++) {
            int col = nt * 8 + tig * 2;
            int ra_ = r0, rb_ = r0 + 8;
            uint2 p01 = make_uint2(f2tf(s[nt][0]), f2tf(s[nt][1]));
            *(uint2*)&Ps[ra_ * 64 + (col ^ ((ra_ & 7) << 2))] = p01;
            uint2 p23 = make_uint2(f2tf(s[nt][2]), f2tf(s[nt][3]));
            *(uint2*)&Ps[rb_ * 64 + (col ^ ((rb_ & 7) << 2))] = p23;
        }
        __syncwarp();

        // O += P V   (P via ldmatrix; V scalar, stride-72 conflict-free)
#pragma unroll
        for (int ks = 0; ks < 8; ks++) {
            int kb = ks * 8;
            uint32_t a0, a1, a2, a3;
            ldsm4(a0, a1, a2, a3, aP + (((2 * ks + khA) ^ lr) << 4));
            int kr0 = kb + tig, kr1 = kb + tig + 4;
            const uint32_t* vrow0 = Vsc + kr0 * VSTR + gid;
            const uint32_t* vrow1 = Vsc + kr1 * VSTR + gid;
#pragma unroll
            for (int nt = 0; nt < 8; nt++) {
                uint32_t b0 = vrow0[nt * 8];
                uint32_t b1 = vrow1[nt * 8];
                mma_tf32(o[nt], a0, a1, a2, a3, b0, b1);
            }
        }
    }

    // epilogue: normalize and store
    float inv0 = 1.f / lr2[0];
    float inv1 = 1.f / lr2[1];
    int t0 = qb * 64 + r0;
    int t1 = t0 + 8;
#pragma unroll
    for (int nt = 0; nt < 8; nt++) {
        int col = h * DH + nt * 8 + tig * 2;
        float2 v0 = make_float2(o[nt][0] * inv0, o[nt][1] * inv0);
        *(float2*)(vals + (size_t)t0 * D + col) = v0;
        float2 v1 = make_float2(o[nt][2] * inv1, o[nt][3] * inv1);
        *(float2*)(vals + (size_t)t1 * D + col) = v1;
    }
}

// ---------------------------------------------------------------------------
extern "C" void kernel_launch(void* const* d_in, const int* in_sizes, int n_in,
                              void* d_out, int out_size)
{
    const float* q     = (const float*)d_in[0];
    const float* k     = (const float*)d_in[1];
    const float* v     = (const float*)d_in[2];
    // d_in[3] = mask (causal tril, known statically — unused)
    const float* freqs = (const float*)d_in[4];
    const float* w_q   = (const float*)d_in[5];
    const float* w_k   = (const float*)d_in[6];
    const float* w_v   = (const float*)d_in[7];
    const float* w_o   = (const float*)d_in[8];
    float* out = (float*)d_out;

    float *Qh, *Kh, *Vh, *Vals;
    cudaGetSymbolAddress((void**)&Qh, g_Qh);
    cudaGetSymbolAddress((void**)&Kh, g_Kh);
    cudaGetSymbolAddress((void**)&Vh, g_Vh);
    cudaGetSymbolAddress((void**)&Vals, g_Vals);

    dim3 pgrid(D / 64, T / 128);  // (16, 32)
    proj_kernel<<<pgrid, 256>>>(q, w_q, freqs, Qh, 1);
    proj_kernel<<<pgrid, 256>>>(k, w_k, freqs, Kh, 1);
    proj_kernel<<<pgrid, 256>>>(v, w_v, freqs, Vh, 1);

    // smem: Q 4096 + K 2*4096 + V 2*64*72 + P 4096 = 25600 words = 100 KB
    size_t smem = (4096 * 4 + 2 * 64 * VSTR) * sizeof(uint32_t);
    cudaFuncSetAttribute(attn_kernel,
                         cudaFuncAttributeMaxDynamicSharedMemorySize, (int)smem);
    attn_kernel<<<dim3(T / 64, H), 128, smem>>>(Qh, Kh, Vh, Vals);

    proj_kernel<<<pgrid, 256>>>(Vals, w_o, nullptr, out, 0);
}

// round 5
// speedup vs baseline: 1.5439x; 1.5439x over previous
#include <cuda_runtime.h>
#include <math.h>
#include <stdint.h>

#define T 4096
#define D 1024
#define H 16
#define DH 64
#define L 32

#define VSTR 72   // V smem row stride in words: 72 % 32 == 8 -> conflict-free scalar reads

// Scratch (allocation-free rule: __device__ globals)
__device__ float g_Qh[H * T * DH];
__device__ float g_Kh[H * T * DH];
__device__ float g_Vh[H * T * DH];
__device__ float g_Vals[T * D];

__device__ __forceinline__ uint32_t f2tf(float f) {
    uint32_t r;
    asm("cvt.rna.tf32.f32 %0, %1;" : "=r"(r) : "f"(f));
    return r;
}

__device__ __forceinline__ void mma_tf32(float c[4], uint32_t a0, uint32_t a1,
                                         uint32_t a2, uint32_t a3,
                                         uint32_t b0, uint32_t b1) {
    asm volatile(
        "mma.sync.aligned.m16n8k8.row.col.f32.tf32.tf32.f32 "
        "{%0,%1,%2,%3}, {%4,%5,%6,%7}, {%8,%9}, {%0,%1,%2,%3};\n"
        : "+f"(c[0]), "+f"(c[1]), "+f"(c[2]), "+f"(c[3])
        : "r"(a0), "r"(a1), "r"(a2), "r"(a3), "r"(b0), "r"(b1));
}

__device__ __forceinline__ void ldsm4(uint32_t& d0, uint32_t& d1, uint32_t& d2,
                                      uint32_t& d3, uint32_t saddr) {
    asm volatile(
        "ldmatrix.sync.aligned.m8n8.x4.shared.b16 {%0,%1,%2,%3}, [%4];"
        : "=r"(d0), "=r"(d1), "=r"(d2), "=r"(d3)
        : "r"(saddr));
}

// ---------------------------------------------------------------------------
// Projection GEMM on tensor cores (tf32) with ldmatrix fragment loads.
// out = X[M,K] @ W[N,K]^T.  M=4096, N=1024, K=1024.
// Block tile 128x64, BK=32. 256 threads = 8 warps (4 M x 2 N), warp tile 32x32.
// mode 0: plain row-major out [T,1024].
// mode 1: RoPE epilogue + head-major out [H][T][DH] (BN==DH so bx == head).
// ---------------------------------------------------------------------------
__global__ __launch_bounds__(256) void proj_kernel(
    const float* __restrict__ X, const float* __restrict__ W,
    const float* __restrict__ freqs, float* __restrict__ out, int mode)
{
    __shared__ uint32_t As[128 * 32];
    __shared__ uint32_t Bs[64 * 32];

    const int tid = threadIdx.x;
    const int lane = tid & 31;
    const int w = tid >> 5;
    const int gid = lane >> 2;   // 0..7
    const int tig = lane & 3;    // 0..3
    const int wm = w >> 1;       // 0..3
    const int wn = w & 1;        // 0..1
    const int bx = blockIdx.x, by = blockIdx.y;

    const int lsub = lane >> 3;
    const int lr = lane & 7;
    const int khA = lsub >> 1;
    const int khB = lsub & 1;

    const uint32_t as_s = (uint32_t)__cvta_generic_to_shared(As);
    const uint32_t bs_s = (uint32_t)__cvta_generic_to_shared(Bs);

    uint32_t aA[2];
#pragma unroll
    for (int mt = 0; mt < 2; mt++) {
        int rowA = wm * 32 + mt * 16 + lr + ((lsub & 1) << 3);
        aA[mt] = as_s + rowA * 128;
    }
    uint32_t bB[2];
#pragma unroll
    for (int np = 0; np < 2; np++) {
        int n = wn * 32 + np * 16 + lr + ((lsub >> 1) << 3);
        bB[np] = bs_s + n * 128;
    }

    float acc[2][4][4];
#pragma unroll
    for (int mt = 0; mt < 2; mt++)
#pragma unroll
        for (int nt = 0; nt < 4; nt++)
#pragma unroll
            for (int r = 0; r < 4; r++) acc[mt][nt][r] = 0.f;

    int am[4], akg[4], bm[2], bkg[2];
#pragma unroll
    for (int i = 0; i < 4; i++) {
        int f = tid + i * 256;
        am[i] = f >> 3;
        akg[i] = f & 7;
    }
#pragma unroll
    for (int i = 0; i < 2; i++) {
        int f = tid + i * 256;
        bm[i] = f >> 3;
        bkg[i] = f & 7;
    }

    float4 ra[4], rb[2];
#pragma unroll
    for (int i = 0; i < 4; i++)
        ra[i] = *(const float4*)(X + (size_t)(by * 128 + am[i]) * D + akg[i] * 4);
#pragma unroll
    for (int i = 0; i < 2; i++)
        rb[i] = *(const float4*)(W + (size_t)(bx * 64 + bm[i]) * D + bkg[i] * 4);

    for (int kk = 0; kk < 32; kk++) {
        __syncthreads();
#pragma unroll
        for (int i = 0; i < 4; i++) {
            uint4 u = make_uint4(f2tf(ra[i].x), f2tf(ra[i].y), f2tf(ra[i].z), f2tf(ra[i].w));
            *(uint4*)&As[am[i] * 32 + ((akg[i] ^ (am[i] & 7)) << 2)] = u;
        }
#pragma unroll
        for (int i = 0; i < 2; i++) {
            uint4 u = make_uint4(f2tf(rb[i].x), f2tf(rb[i].y), f2tf(rb[i].z), f2tf(rb[i].w));
            *(uint4*)&Bs[bm[i] * 32 + ((bkg[i] ^ (bm[i] & 7)) << 2)] = u;
        }
        __syncthreads();

        if (kk < 31) {
            int k0 = (kk + 1) * 32;
#pragma unroll
            for (int i = 0; i < 4; i++)
                ra[i] = *(const float4*)(X + (size_t)(by * 128 + am[i]) * D + k0 + akg[i] * 4);
#pragma unroll
            for (int i = 0; i < 2; i++)
                rb[i] = *(const float4*)(W + (size_t)(bx * 64 + bm[i]) * D + k0 + bkg[i] * 4);
        }

#pragma unroll
        for (int ks = 0; ks < 4; ks++) {
            uint32_t a[2][4];
#pragma unroll
            for (int mt = 0; mt < 2; mt++)
                ldsm4(a[mt][0], a[mt][1], a[mt][2], a[mt][3],
                      aA[mt] + (((2 * ks + khA) ^ lr) << 4));
#pragma unroll
            for (int np = 0; np < 2; np++) {
                uint32_t b00, b01, b10, b11;
                ldsm4(b00, b01, b10, b11, bB[np] + (((2 * ks + khB) ^ lr) << 4));
#pragma unroll
                for (int mt = 0; mt < 2; mt++) {
                    mma_tf32(acc[mt][2 * np], a[mt][0], a[mt][1], a[mt][2], a[mt][3], b00, b01);
                    mma_tf32(acc[mt][2 * np + 1], a[mt][0], a[mt][1], a[mt][2], a[mt][3], b10, b11);
                }
            }
        }
    }

    if (mode == 0) {
#pragma unroll
        for (int mt = 0; mt < 2; mt++) {
#pragma unroll
            for (int rh = 0; rh < 2; rh++) {
                int t = by * 128 + wm * 32 + mt * 16 + gid + rh * 8;
#pragma unroll
                for (int nt = 0; nt < 4; nt++) {
                    int col = bx * 64 + wn * 32 + nt * 8 + tig * 2;
                    float2 v = make_float2(acc[mt][nt][rh * 2], acc[mt][nt][rh * 2 + 1]);
                    *(float2*)(out + (size_t)t * D + col) = v;
                }
            }
        }
    } else {
        const int h = bx;
        if (wn == 0) {
#pragma unroll
            for (int mt = 0; mt < 2; mt++) {
#pragma unroll
                for (int rh = 0; rh < 2; rh++) {
                    int t = by * 128 + wm * 32 + mt * 16 + gid + rh * 8;
#pragma unroll
                    for (int nt = 0; nt < 4; nt++) {
                        int l = nt * 8 + tig * 2;
                        float2 f2 = *(const float2*)(freqs + (size_t)t * L + l);
                        float x0 = acc[mt][nt][rh * 2];
                        float x1 = acc[mt][nt][rh * 2 + 1];
                        float p0 = acc[mt][nt ^ 2][rh * 2];
                        float p1 = acc[mt][nt ^ 2][rh * 2 + 1];
                        float r0 = (nt < 2) ? -p0 : p0;
                        float r1 = (nt < 2) ? -p1 : p1;
                        float2 v;
                        v.x = x0 * __cosf(f2.x) + r0 * __sinf(f2.x);
                        v.y = x1 * __cosf(f2.y) + r1 * __sinf(f2.y);
                        *(float2*)(out + (size_t)h * T * DH + (size_t)t * DH + l) = v;
                    }
                }
            }
        } else {
#pragma unroll
            for (int mt = 0; mt < 2; mt++) {
#pragma unroll
                for (int rh = 0; rh < 2; rh++) {
                    int t = by * 128 + wm * 32 + mt * 16 + gid + rh * 8;
#pragma unroll
                    for (int nt = 0; nt < 4; nt++) {
                        int col = 32 + nt * 8 + tig * 2;
                        float2 v = make_float2(acc[mt][nt][rh * 2], acc[mt][nt][rh * 2 + 1]);
                        *(float2*)(out + (size_t)h * T * DH + (size_t)t * DH + col) = v;
                    }
                }
            }
        }
    }
}

// ---------------------------------------------------------------------------
// Causal flash attention, tf32 tensor cores + ldmatrix.
// Block = (head, 128-query tile), 128 threads = 4 warps, each warp 32 q-rows
// (2 mt sub-tiles of 16) -> every K/V B-fragment feeds 2 MMAs.
// KV tiles of 64; synchronous LDG->STS (RNA tf32 at fill).
// ---------------------------------------------------------------------------
__global__ __launch_bounds__(128) void attn_kernel(
    const float* __restrict__ Q, const float* __restrict__ Kg,
    const float* __restrict__ Vg, float* __restrict__ vals)
{
    extern __shared__ uint32_t sm[];
    uint32_t* Qs = sm;                 // 128x64, xor-swizzled     (8192 w)
    uint32_t* Ks = sm + 8192;          // 64x64, xor-swizzled      (4096 w)
    uint32_t* Vs = sm + 12288;         // 64 rows x VSTR           (4608 w)
    uint32_t* Ps = sm + 16896;         // 128x64, xor-swizzled     (8192 w)

    const int tid = threadIdx.x;
    const int lane = tid & 31;
    const int w = tid >> 5;
    const int gid = lane >> 2;
    const int tig = lane & 3;
    const int b = 31 - blockIdx.x;     // long tiles first
    const int h = blockIdx.y;

    const int lsub = lane >> 3;
    const int lr = lane & 7;
    const int khA = lsub >> 1;
    const int khB = lsub & 1;

    const uint32_t qs_s = (uint32_t)__cvta_generic_to_shared(Qs);
    const uint32_t ks_s = (uint32_t)__cvta_generic_to_shared(Ks);
    const uint32_t ps_s = (uint32_t)__cvta_generic_to_shared(Ps);

    uint32_t aQ[2], aP[2];
#pragma unroll
    for (int mt = 0; mt < 2; mt++) {
        int rowA = w * 32 + mt * 16 + lr + ((lsub & 1) << 3);
        aQ[mt] = qs_s + rowA * 256;
        aP[mt] = ps_s + rowA * 256;
    }
    const int rowBr = lr + ((lsub >> 1) << 3);
    uint32_t bK[4];
#pragma unroll
    for (int np = 0; np < 4; np++)
        bK[np] = ks_s + (np * 16 + rowBr) * 256;

    const float* Qh = Q + (size_t)h * T * DH;
    const float* Kh = Kg + (size_t)h * T * DH;
    const float* Vh = Vg + (size_t)h * T * DH;

    // Q tile: 128 rows, LDG + RNA tf32 (pre-scaled) + swizzled STS
#pragma unroll
    for (int i = 0; i < 16; i++) {
        int f = tid + i * 128;
        int m = f >> 4, kg = f & 15;
        float4 v4 = *(const float4*)(Qh + (size_t)(b * 128 + m) * DH + kg * 4);
        uint4 u = make_uint4(f2tf(v4.x * 0.125f), f2tf(v4.y * 0.125f),
                             f2tf(v4.z * 0.125f), f2tf(v4.w * 0.125f));
        *(uint4*)&Qs[m * 64 + ((kg ^ (m & 7)) << 2)] = u;
    }

    float o[2][8][4];
#pragma unroll
    for (int mt = 0; mt < 2; mt++)
#pragma unroll
        for (int nt = 0; nt < 8; nt++)
#pragma unroll
            for (int r = 0; r < 4; r++) o[mt][nt][r] = 0.f;
    float mr[2][2] = {{-1e30f, -1e30f}, {-1e30f, -1e30f}};
    float lr2[2][2] = {{0.f, 0.f}, {0.f, 0.f}};

    const int n_iters = 2 * b + 2;

    for (int jb = 0; jb < n_iters; jb++) {
        __syncthreads();   // prior iter's K/V reads complete
        // K/V tile fill: 64 rows each, synchronous
#pragma unroll
        for (int i = 0; i < 8; i++) {
            int f = tid + i * 128;
            int m = f >> 4, kg = f & 15;
            float4 k4 = *(const float4*)(Kh + (size_t)(jb * 64 + m) * DH + kg * 4);
            uint4 uk = make_uint4(f2tf(k4.x), f2tf(k4.y), f2tf(k4.z), f2tf(k4.w));
            *(uint4*)&Ks[m * 64 + ((kg ^ (m & 7)) << 2)] = uk;
            float4 v4 = *(const float4*)(Vh + (size_t)(jb * 64 + m) * DH + kg * 4);
            uint4 uv = make_uint4(f2tf(v4.x), f2tf(v4.y), f2tf(v4.z), f2tf(v4.w));
            *(uint4*)&Vs[m * VSTR + kg * 4] = uv;
        }
        __syncthreads();

        // S = Q K^T   (32 x 64 per warp, B fragments reused across mt)
        float s[2][8][4];
#pragma unroll
        for (int mt = 0; mt < 2; mt++)
#pragma unroll
            for (int nt = 0; nt < 8; nt++)
#pragma unroll
                for (int r = 0; r < 4; r++) s[mt][nt][r] = 0.f;

#pragma unroll
        for (int ks = 0; ks < 8; ks++) {
            uint32_t a[2][4];
#pragma unroll
            for (int mt = 0; mt < 2; mt++)
                ldsm4(a[mt][0], a[mt][1], a[mt][2], a[mt][3],
                      aQ[mt] + (((2 * ks + khA) ^ lr) << 4));
#pragma unroll
            for (int np = 0; np < 4; np++) {
                uint32_t b00, b01, b10, b11;
                ldsm4(b00, b01, b10, b11, bK[np] + (((2 * ks + khB) ^ lr) << 4));
#pragma unroll
                for (int mt = 0; mt < 2; mt++) {
                    mma_tf32(s[mt][2 * np], a[mt][0], a[mt][1], a[mt][2], a[mt][3], b00, b01);
                    mma_tf32(s[mt][2 * np + 1], a[mt][0], a[mt][1], a[mt][2], a[mt][3], b10, b11);
                }
            }
        }

        // causal mask (only the last two KV tiles can cross the diagonal)
        if (jb >= 2 * b) {
#pragma unroll
            for (int mt = 0; mt < 2; mt++)
#pragma unroll
                for (int nt = 0; nt < 8; nt++)
#pragma unroll
                    for (int r = 0; r < 4; r++) {
                        int col = jb * 64 + nt * 8 + tig * 2 + (r & 1);
                        int row = b * 128 + w * 32 + mt * 16 + gid + ((r & 2) ? 8 : 0);
                        if (col > row) s[mt][nt][r] = -1e30f;
                    }
        }

        // online softmax (two rows per thread per mt)
#pragma unroll
        for (int mt = 0; mt < 2; mt++) {
#pragma unroll
            for (int half = 0; half < 2; half++) {
                float mx = -1e30f;
#pragma unroll
                for (int nt = 0; nt < 8; nt++) {
                    mx = fmaxf(mx, s[mt][nt][half * 2]);
                    mx = fmaxf(mx, s[mt][nt][half * 2 + 1]);
                }
                mx = fmaxf(mx, __shfl_xor_sync(0xffffffffu, mx, 1));
                mx = fmaxf(mx, __shfl_xor_sync(0xffffffffu, mx, 2));
                float mnew = fmaxf(mr[mt][half], mx);
                float alpha = __expf(mr[mt][half] - mnew);
                mr[mt][half] = mnew;
                float rs = 0.f;
#pragma unroll
                for (int nt = 0; nt < 8; nt++) {
                    float p0 = __expf(s[mt][nt][half * 2] - mnew);
                    float p1 = __expf(s[mt][nt][half * 2 + 1] - mnew);
                    s[mt][nt][half * 2] = p0;
                    s[mt][nt][half * 2 + 1] = p1;
                    rs += p0 + p1;
                }
                rs += __shfl_xor_sync(0xffffffffu, rs, 1);
                rs += __shfl_xor_sync(0xffffffffu, rs, 2);
                lr2[mt][half] = lr2[mt][half] * alpha + rs;
#pragma unroll
                for (int nt = 0; nt < 8; nt++) {
                    o[mt][nt][half * 2] *= alpha;
                    o[mt][nt][half * 2 + 1] *= alpha;
                }
            }

            // write P (RNA tf32) to warp-private smem rows
            int ra_ = w * 32 + mt * 16 + gid;
            int rb_ = ra_ + 8;
#pragma unroll
            for (int nt = 0; nt < 8; nt++) {
                int col = nt * 8 + tig * 2;
                uint2 p01 = make_uint2(f2tf(s[mt][nt][0]), f2tf(s[mt][nt][1]));
                *(uint2*)&Ps[ra_ * 64 + (col ^ ((ra_ & 7) << 2))] = p01;
                uint2 p23 = make_uint2(f2tf(s[mt][nt][2]), f2tf(s[mt][nt][3]));
                *(uint2*)&Ps[rb_ * 64 + (col ^ ((rb_ & 7) << 2))] = p23;
            }
        }
        __syncwarp();

        // O += P V   (P via ldmatrix; V scalar, stride-72 conflict-free;
        //             V fragments reused across mt)
#pragma unroll
        for (int ks = 0; ks < 8; ks++) {
            int kb = ks * 8;
            uint32_t a[2][4];
#pragma unroll
            for (int mt = 0; mt < 2; mt++)
                ldsm4(a[mt][0], a[mt][1], a[mt][2], a[mt][3],
                      aP[mt] + (((2 * ks + khA) ^ lr) << 4));
            int kr0 = kb + tig, kr1 = kb + tig + 4;
            const uint32_t* vrow0 = Vs + kr0 * VSTR + gid;
            const uint32_t* vrow1 = Vs + kr1 * VSTR + gid;
#pragma unroll
            for (int nt = 0; nt < 8; nt++) {
                uint32_t b0 = vrow0[nt * 8];
                uint32_t b1 = vrow1[nt * 8];
#pragma unroll
                for (int mt = 0; mt < 2; mt++)
                    mma_tf32(o[mt][nt], a[mt][0], a[mt][1], a[mt][2], a[mt][3], b0, b1);
            }
        }
    }

    // epilogue: normalize and store
#pragma unroll
    for (int mt = 0; mt < 2; mt++) {
        float inv0 = 1.f / lr2[mt][0];
        float inv1 = 1.f / lr2[mt][1];
        int t0 = b * 128 + w * 32 + mt * 16 + gid;
        int t1 = t0 + 8;
#pragma unroll
        for (int nt = 0; nt < 8; nt++) {
            int col = h * DH + nt * 8 + tig * 2;
            float2 v0 = make_float2(o[mt][nt][0] * inv0, o[mt][nt][1] * inv0);
            *(float2*)(vals + (size_t)t0 * D + col) = v0;
            float2 v1 = make_float2(o[mt][nt][2] * inv1, o[mt][nt][3] * inv1);
            *(float2*)(vals + (size_t)t1 * D + col) = v1;
        }
    }
}

// ---------------------------------------------------------------------------
extern "C" void kernel_launch(void* const* d_in, const int* in_sizes, int n_in,
                              void* d_out, int out_size)
{
    const float* q     = (const float*)d_in[0];
    const float* k     = (const float*)d_in[1];
    const float* v     = (const float*)d_in[2];
    // d_in[3] = mask (causal tril, known statically — unused)
    const float* freqs = (const float*)d_in[4];
    const float* w_q   = (const float*)d_in[5];
    const float* w_k   = (const float*)d_in[6];
    const float* w_v   = (const float*)d_in[7];
    const float* w_o   = (const float*)d_in[8];
    float* out = (float*)d_out;

    float *Qh, *Kh, *Vh, *Vals;
    cudaGetSymbolAddress((void**)&Qh, g_Qh);
    cudaGetSymbolAddress((void**)&Kh, g_Kh);
    cudaGetSymbolAddress((void**)&Vh, g_Vh);
    cudaGetSymbolAddress((void**)&Vals, g_Vals);

    dim3 pgrid(D / 64, T / 128);  // (16, 32)
    proj_kernel<<<pgrid, 256>>>(q, w_q, freqs, Qh, 1);
    proj_kernel<<<pgrid, 256>>>(k, w_k, freqs, Kh, 1);
    proj_kernel<<<pgrid, 256>>>(v, w_v, freqs, Vh, 1);

    // smem: Q 8192 + K 4096 + V 4608 + P 8192 = 25088 words = 100352 B
    size_t smem = 25088 * sizeof(uint32_t);
    cudaFuncSetAttribute(attn_kernel,
                         cudaFuncAttributeMaxDynamicSharedMemorySize, (int)smem);
    attn_kernel<<<dim3(T / 128, H), 128, smem>>>(Qh, Kh, Vh, Vals);

    proj_kernel<<<pgrid, 256>>>(Vals, w_o, nullptr, out, 0);
}